// round 6
// baseline (speedup 1.0000x reference)
#include <cuda_runtime.h>
#include <cstdint>

#define DIM   768
#define POOL  20
#define TOPK  9
#define NVEC  6                  // float4 chunks per lane: 768/4/32
#define THREADS 512
#define WARPS   (THREADS / 32)   // 16 rows per block
#define ROW_BYTES (DIM * 4)      // 3072
#define PROMPT_F4 (POOL * DIM / 4)  // 3840 float4 = 60KB

// Allocation-free scratch
__device__ float        g_kn[POOL * DIM];   // normalized keys
__device__ float        g_rowsum[POOL];
__device__ unsigned int g_count[POOL];
__device__ unsigned int g_done = 0;

// ---------------------------------------------------------------------------
// prep: 1 block x 640 threads. Warp w normalizes key row w.
// ---------------------------------------------------------------------------
__global__ void prep_kernel(const float* __restrict__ keys,
                            const int*   __restrict__ layer)
{
    const int w    = threadIdx.x >> 5;
    const int lane = threadIdx.x & 31;
    if (w < POOL) {
        const float* __restrict__ krow =
            keys + ((size_t)(*layer) * POOL + w) * DIM;
        float ss = 0.f;
        #pragma unroll
        for (int i = 0; i < DIM / 32; i++) {
            float v = __ldg(krow + lane + 32 * i);
            ss += v * v;
        }
        #pragma unroll
        for (int off = 16; off; off >>= 1)
            ss += __shfl_xor_sync(0xffffffffu, ss, off);
        const float inv = 1.f / fmaxf(sqrtf(ss), 1e-12f);
        #pragma unroll
        for (int i = 0; i < DIM / 32; i++)
            g_kn[w * DIM + lane + 32 * i] = __ldg(krow + lane + 32 * i) * inv;
    }
    if (threadIdx.x < POOL) {
        g_count[threadIdx.x]  = 0u;
        g_rowsum[threadIdx.x] = 0.f;
    }
}

// ---------------------------------------------------------------------------
// top-9 on a 20-vector in registers (strict '>' matches lax.top_k tie rule)
// ---------------------------------------------------------------------------
__device__ __forceinline__ uint64_t topk_pack(float* s)
{
    uint64_t packed = 0;
    #pragma unroll
    for (int t = 0; t < TOPK; t++) {
        float best = -3.4e38f; int bj = 0;
        #pragma unroll
        for (int j = 0; j < POOL; j++)
            if (s[j] > best) { best = s[j]; bj = j; }
        packed |= (uint64_t)bj << (7 * t);
        #pragma unroll
        for (int j = 0; j < POOL; j++)
            if (j == bj) s[j] = -3.4e38f;
    }
    return packed;
}

// ---------------------------------------------------------------------------
// main: warp-per-row compute; gather emitted as 1-D bulk SMEM->GMEM copies.
// ---------------------------------------------------------------------------
__global__ void __launch_bounds__(THREADS, 2)
pool_main(const float* __restrict__ x,
          const float* __restrict__ prompts,
          const int*   __restrict__ layer,
          float*       __restrict__ out,
          int B, long long total, long long out_sz)
{
    extern __shared__ float4 s_prompts[];     // 60 KB staged prompt pool
    __shared__ unsigned int s_count[POOL];
    __shared__ unsigned int s_last;

    if (threadIdx.x < POOL) s_count[threadIdx.x] = 0u;

    // stage prompts[layer] into smem (L2-resident source)
    {
        const float4* __restrict__ pbase =
            (const float4*)(prompts + (size_t)(*layer) * POOL * DIM);
        for (int i = threadIdx.x; i < PROMPT_F4; i += THREADS)
            s_prompts[i] = __ldg(pbase + i);
    }
    __syncthreads();
    // order generic smem writes before async-proxy (bulk copy) reads
    asm volatile("fence.proxy.async.shared::cta;" ::: "memory");

    uint32_t s_base;
    asm("{ .reg .u64 t; cvta.to.shared.u64 t, %1; cvt.u32.u64 %0, t; }"
        : "=r"(s_base) : "l"((const void*)s_prompts));

    const int warp = threadIdx.x >> 5;
    const int lane = threadIdx.x & 31;
    const int row  = blockIdx.x * WARPS + warp;
    bool issued = false;

    if (row < B) {
        const float4* __restrict__ xr  = (const float4*)(x + (size_t)row * DIM);
        const float4* __restrict__ knv = (const float4*)g_kn;

        float s[POOL];
        #pragma unroll
        for (int j = 0; j < POOL; j++) s[j] = 0.f;
        float ss = 0.f;

        #pragma unroll
        for (int i = 0; i < NVEC; i++) {
            const float4 xv = __ldcs(xr + lane + 32 * i);
            ss += xv.x * xv.x + xv.y * xv.y + xv.z * xv.z + xv.w * xv.w;
            #pragma unroll
            for (int j = 0; j < POOL; j++) {
                const float4 kv = __ldg(knv + j * (DIM / 4) + lane + 32 * i);
                s[j] += xv.x * kv.x + xv.y * kv.y + xv.z * kv.z + xv.w * kv.w;
            }
        }

        // butterfly reduce 21 accumulators
        #pragma unroll
        for (int off = 16; off; off >>= 1) {
            ss += __shfl_xor_sync(0xffffffffu, ss, off);
            #pragma unroll
            for (int j = 0; j < POOL; j++)
                s[j] += __shfl_xor_sync(0xffffffffu, s[j], off);
        }

        const float inv = 1.f / fmaxf(sqrtf(ss), 1e-12f);
        #pragma unroll
        for (int j = 0; j < POOL; j++) s[j] *= inv;

        if (lane == 0 && row < POOL) {
            float rs = 0.f;
            #pragma unroll
            for (int j = 0; j < POOL; j++) rs += s[j];
            g_rowsum[row] = rs;
        }

        const uint64_t packed = topk_pack(s);   // redundant across lanes, cheap

        if (lane == 0) {
            #pragma unroll
            for (int t = 0; t < TOPK; t++)
                atomicAdd(&s_count[(int)((packed >> (7 * t)) & 127)], 1u);
        }

        // gather: lane t emits a 3 KB bulk copy smem(prompt id) -> out(row,t)
        if (lane < TOPK) {
            const int id = (int)((packed >> (7 * lane)) & 127);
            const uint32_t src = s_base + (uint32_t)id * ROW_BYTES;
            float* dst = out + ((size_t)row * TOPK + lane) * DIM;
            asm volatile(
                "cp.async.bulk.global.shared::cta.bulk_group [%0], [%1], %2;"
                :: "l"(dst), "r"(src), "n"(ROW_BYTES) : "memory");
            asm volatile("cp.async.bulk.commit_group;" ::: "memory");
            issued = true;
        }
    }

    __syncthreads();
    if (threadIdx.x < POOL)
        atomicAdd(&g_count[threadIdx.x], s_count[threadIdx.x]);

    // last-block finalize: dist = 1 - sum_r count[r]*rowsum[r] / (B*9*20)
    __threadfence();
    if (threadIdx.x == 0)
        s_last = (atomicAdd(&g_done, 1u) == gridDim.x - 1) ? 1u : 0u;
    __syncthreads();
    if (s_last && threadIdx.x == 0) {
        double acc = 0.0;
        #pragma unroll
        for (int r = 0; r < POOL; r++)
            acc += (double)g_count[r] * (double)g_rowsum[r];
        const float dist = (float)(1.0 - acc / ((double)B * TOPK * POOL));
        for (long long i = total; i < out_sz; i++) out[i] = dist;
        g_done = 0;   // reset for next graph replay
    }

    // bulk stores read smem asynchronously: wait before smem is deallocated
    if (issued)
        asm volatile("cp.async.bulk.wait_group 0;" ::: "memory");
}

extern "C" void kernel_launch(void* const* d_in, const int* in_sizes, int n_in,
                              void* d_out, int out_size)
{
    const float* x       = (const float*)d_in[0];
    const float* keys    = (const float*)d_in[1];
    const float* prompts = (const float*)d_in[2];
    const int*   layer   = (const int*)d_in[3];

    const int B = in_sizes[0] / DIM;
    const long long total = (long long)B * TOPK * DIM;
    const int smem = PROMPT_F4 * sizeof(float4);   // 61440

    static int configured = 0;
    if (!configured) {
        cudaFuncSetAttribute(pool_main,
                             cudaFuncAttributeMaxDynamicSharedMemorySize, smem);
        configured = 1;
    }

    prep_kernel<<<1, 640>>>(keys, layer);
    pool_main<<<(B + WARPS - 1) / WARPS, THREADS, smem>>>(
        x, prompts, layer, (float*)d_out, B, total, (long long)out_size);
}

// round 7
// speedup vs baseline: 1.1845x; 1.1845x over previous
#include <cuda_runtime.h>
#include <cstdint>

#define DIM   768
#define POOL  20
#define TOPK  9
#define NVEC  6                 // float4 chunks per lane: 768/4/32
#define ROWS_PER_WARP 2
#define BLOCKS 444              // 148 SMs x 3 resident CTAs

// Allocation-free scratch
__device__ float        g_kn[POOL * DIM];
__device__ float        g_rowsum[POOL];
__device__ unsigned int g_count[POOL];
__device__ unsigned int g_done = 0;

// ---------------------------------------------------------------------------
// prep: 1 block x 640 threads. Warp w normalizes key row w (shuffle-only).
// ---------------------------------------------------------------------------
__global__ void prep_kernel(const float* __restrict__ keys,
                            const int*   __restrict__ layer)
{
    const int w    = threadIdx.x >> 5;
    const int lane = threadIdx.x & 31;
    if (w < POOL) {
        const float* __restrict__ krow =
            keys + ((size_t)(*layer) * POOL + w) * DIM;
        float ss = 0.f;
        #pragma unroll
        for (int i = 0; i < DIM / 32; i++) {
            float v = __ldg(krow + lane + 32 * i);
            ss += v * v;
        }
        #pragma unroll
        for (int off = 16; off; off >>= 1)
            ss += __shfl_xor_sync(0xffffffffu, ss, off);
        const float inv = 1.f / fmaxf(sqrtf(ss), 1e-12f);
        #pragma unroll
        for (int i = 0; i < DIM / 32; i++)
            g_kn[w * DIM + lane + 32 * i] = __ldg(krow + lane + 32 * i) * inv;
    }
    if (threadIdx.x < POOL) {
        g_count[threadIdx.x]  = 0u;
        g_rowsum[threadIdx.x] = 0.f;
    }
}

// ---------------------------------------------------------------------------
// top-9 on a 20-vector in registers (strict '>' matches lax.top_k ties)
// ---------------------------------------------------------------------------
__device__ __forceinline__ uint64_t topk_pack(float* s)
{
    uint64_t packed = 0;
    #pragma unroll
    for (int t = 0; t < TOPK; t++) {
        float best = -3.4e38f; int bj = 0;
        #pragma unroll
        for (int j = 0; j < POOL; j++)
            if (s[j] > best) { best = s[j]; bj = j; }
        packed |= (uint64_t)bj << (7 * t);
        #pragma unroll
        for (int j = 0; j < POOL; j++)
            if (j == bj) s[j] = -3.4e38f;
    }
    return packed;
}

// ---------------------------------------------------------------------------
// main: persistent warps grid-stride over row PAIRS; no barrier in the loop.
// ---------------------------------------------------------------------------
__global__ void __launch_bounds__(256, 3)
pool_main(const float* __restrict__ x,
          const float* __restrict__ prompts,
          const int*   __restrict__ layer,
          float*       __restrict__ out,
          int B, long long total, long long out_sz)
{
    __shared__ unsigned int s_count[POOL];
    __shared__ unsigned int s_last;
    if (threadIdx.x < POOL) s_count[threadIdx.x] = 0u;
    __syncthreads();

    const int warp  = threadIdx.x >> 5;
    const int lane  = threadIdx.x & 31;
    const int nwarp = (gridDim.x * blockDim.x) >> 5;
    const int gw    = blockIdx.x * (blockDim.x >> 5) + warp;
    const int npair = B >> 1;                     // B = 32768 -> 16384 pairs

    const float4* __restrict__ knv = (const float4*)g_kn;
    const float4* __restrict__ pbase =
        (const float4*)(prompts + (size_t)(*layer) * POOL * DIM);

    for (int pair = gw; pair < npair; pair += nwarp) {
        const int r0 = pair * 2;
        const int r1 = r0 + 1;

        const float4* __restrict__ xr0 = (const float4*)(x + (size_t)r0 * DIM);
        const float4* __restrict__ xr1 = (const float4*)(x + (size_t)r1 * DIM);

        float s0[POOL], s1[POOL];
        #pragma unroll
        for (int j = 0; j < POOL; j++) { s0[j] = 0.f; s1[j] = 0.f; }
        float ss0 = 0.f, ss1 = 0.f;

        #pragma unroll
        for (int i = 0; i < NVEC; i++) {
            const float4 xv0 = __ldcs(xr0 + lane + 32 * i);
            const float4 xv1 = __ldcs(xr1 + lane + 32 * i);
            ss0 += xv0.x * xv0.x + xv0.y * xv0.y + xv0.z * xv0.z + xv0.w * xv0.w;
            ss1 += xv1.x * xv1.x + xv1.y * xv1.y + xv1.z * xv1.z + xv1.w * xv1.w;
            #pragma unroll
            for (int j = 0; j < POOL; j++) {
                const float4 kv = __ldg(knv + j * (DIM / 4) + lane + 32 * i);
                s0[j] += xv0.x * kv.x + xv0.y * kv.y + xv0.z * kv.z + xv0.w * kv.w;
                s1[j] += xv1.x * kv.x + xv1.y * kv.y + xv1.z * kv.z + xv1.w * kv.w;
            }
        }

        // butterfly reduce all 42 accumulators
        #pragma unroll
        for (int off = 16; off; off >>= 1) {
            ss0 += __shfl_xor_sync(0xffffffffu, ss0, off);
            ss1 += __shfl_xor_sync(0xffffffffu, ss1, off);
            #pragma unroll
            for (int j = 0; j < POOL; j++) {
                s0[j] += __shfl_xor_sync(0xffffffffu, s0[j], off);
                s1[j] += __shfl_xor_sync(0xffffffffu, s1[j], off);
            }
        }

        const float inv0 = 1.f / fmaxf(sqrtf(ss0), 1e-12f);
        const float inv1 = 1.f / fmaxf(sqrtf(ss1), 1e-12f);
        #pragma unroll
        for (int j = 0; j < POOL; j++) { s0[j] *= inv0; s1[j] *= inv1; }

        // dist bookkeeping: pool-sums of sim rows 0..19
        if (lane == 0) {
            if (r0 < POOL) {
                float rs = 0.f;
                #pragma unroll
                for (int j = 0; j < POOL; j++) rs += s0[j];
                g_rowsum[r0] = rs;
            }
            if (r1 < POOL) {
                float rs = 0.f;
                #pragma unroll
                for (int j = 0; j < POOL; j++) rs += s1[j];
                g_rowsum[r1] = rs;
            }
        }

        const uint64_t p0 = topk_pack(s0);
        const uint64_t p1 = topk_pack(s1);

        if (lane == 0) {
            #pragma unroll
            for (int t = 0; t < TOPK; t++) {
                atomicAdd(&s_count[(int)((p0 >> (7 * t)) & 127)], 1u);
                atomicAdd(&s_count[(int)((p1 >> (7 * t)) & 127)], 1u);
            }
        }

        // gather: 18 prompt-row copies, coalesced streaming stores
        float4* __restrict__ o0 = (float4*)out + (size_t)r0 * (TOPK * DIM / 4);
        float4* __restrict__ o1 = (float4*)out + (size_t)r1 * (TOPK * DIM / 4);
        #pragma unroll
        for (int t = 0; t < TOPK; t++) {
            const float4* pr0 = pbase + (int)((p0 >> (7 * t)) & 127) * (DIM / 4);
            const float4* pr1 = pbase + (int)((p1 >> (7 * t)) & 127) * (DIM / 4);
            #pragma unroll
            for (int i = 0; i < NVEC; i++) {
                __stcs(o0 + t * (DIM / 4) + lane + 32 * i, __ldg(pr0 + lane + 32 * i));
                __stcs(o1 + t * (DIM / 4) + lane + 32 * i, __ldg(pr1 + lane + 32 * i));
            }
        }
    }

    __syncthreads();
    if (threadIdx.x < POOL)
        atomicAdd(&g_count[threadIdx.x], s_count[threadIdx.x]);

    // last-block finalize: dist = 1 - sum_r count[r]*rowsum[r] / (B*9*20)
    __threadfence();
    if (threadIdx.x == 0)
        s_last = (atomicAdd(&g_done, 1u) == gridDim.x - 1) ? 1u : 0u;
    __syncthreads();
    if (s_last && threadIdx.x == 0) {
        double acc = 0.0;
        #pragma unroll
        for (int r = 0; r < POOL; r++)
            acc += (double)g_count[r] * (double)g_rowsum[r];
        const float dist = (float)(1.0 - acc / ((double)B * TOPK * POOL));
        for (long long i = total; i < out_sz; i++) out[i] = dist;
        g_done = 0;   // reset for next graph replay
    }
}

extern "C" void kernel_launch(void* const* d_in, const int* in_sizes, int n_in,
                              void* d_out, int out_size)
{
    const float* x       = (const float*)d_in[0];
    const float* keys    = (const float*)d_in[1];
    const float* prompts = (const float*)d_in[2];
    const int*   layer   = (const int*)d_in[3];

    const int B = in_sizes[0] / DIM;
    const long long total = (long long)B * TOPK * DIM;

    const int npair  = B >> 1;
    const int wneed  = (npair + 0);             // one warp per pair min
    int blocks = BLOCKS;
    const int maxblk = (wneed + 7) / 8;         // 8 warps per block
    if (blocks > maxblk) blocks = maxblk;

    prep_kernel<<<1, 640>>>(keys, layer);
    pool_main<<<blocks, 256>>>(x, prompts, layer, (float*)d_out,
                               B, total, (long long)out_size);
}